// round 1
// baseline (speedup 1.0000x reference)
#include <cuda_runtime.h>
#include <cstdint>

#define W_IMG 2048
#define H_IMG 2048
#define NPIX (W_IMG * H_IMG)

// state codes: 0 = none, 1 = weak (unclaimed), 2 = weak claimed as edge, 3 = strong (edge)
__device__ __align__(16) unsigned char g_state[NPIX];
__device__ unsigned int g_queue[NPIX];   // zero-init at load; consumers re-zero their slots
__device__ unsigned int g_tail;
__device__ unsigned int g_head;
__device__ unsigned int g_processed;

__global__ void k_reset() {
    g_tail = 0u;
    g_head = 0u;
    g_processed = 0u;
}

// ---------------------------------------------------------------------------
// Atomic byte CAS 1 -> 2 on g_state via 32-bit word CAS.
// ---------------------------------------------------------------------------
__device__ __forceinline__ bool claim_weak(unsigned idx) {
    unsigned* wa = reinterpret_cast<unsigned*>(g_state) + (idx >> 2);
    unsigned sh = (idx & 3u) * 8u;
    unsigned old = *(volatile unsigned*)wa;
    while (((old >> sh) & 0xFFu) == 1u) {
        unsigned des = (old & ~(0xFFu << sh)) | (2u << sh);
        unsigned prev = atomicCAS(wa, old, des);
        if (prev == old) return true;
        old = prev;
    }
    return false;
}

// ---------------------------------------------------------------------------
// DFS expansion from an edge pixel through weak pixels (8-connected).
// Weak/strong pixels are always interior (NMS interior mask), so all 8
// neighbors are in-bounds. Local stack; rare overflow spills to global queue.
// ---------------------------------------------------------------------------
#define DFS_STACK 128

__device__ void dfs_expand(unsigned pix) {
    unsigned stack[DFS_STACK];
    int sp = 0;
    unsigned cur = pix;
    for (;;) {
        const int offs[8] = {-W_IMG - 1, -W_IMG, -W_IMG + 1, -1, 1,
                             W_IMG - 1, W_IMG, W_IMG + 1};
#pragma unroll
        for (int k = 0; k < 8; k++) {
            unsigned n = cur + (unsigned)offs[k];
            if (((volatile unsigned char*)g_state)[n] == 1u) {
                if (claim_weak(n)) {
                    if (sp < DFS_STACK) {
                        stack[sp++] = n;
                    } else {
                        unsigned pos = atomicAdd(&g_tail, 1u);
                        ((volatile unsigned*)g_queue)[pos] = n + 1u;  // publish (nonzero)
                    }
                }
            }
        }
        if (sp == 0) break;
        cur = stack[--sp];
    }
}

// ---------------------------------------------------------------------------
// K1: fused quantize + Sobel + L1 mag + direction-binned NMS + double threshold
// ---------------------------------------------------------------------------
#define TX 32
#define TY 16

__global__ __launch_bounds__(TX* TY) void k_grad(const float* __restrict__ x) {
    __shared__ float simg[TY + 4][TX + 4];     // 20 x 36 quantized image w/ 2-halo
    __shared__ float smag[TY + 2][TX + 2 + 1]; // 18 x 34(+pad) magnitude w/ 1-halo

    const int tx = threadIdx.x, ty = threadIdx.y;
    const int bx = blockIdx.x * TX, by = blockIdx.y * TY;
    const int tid = ty * TX + tx;
    const int NT = TX * TY;

    // Load quantized image with replicate border (clamped coords)
    for (int i = tid; i < (TY + 4) * (TX + 4); i += NT) {
        int ly = i / (TX + 4), lx = i % (TX + 4);
        int gy = min(max(by + ly - 2, 0), H_IMG - 1);
        int gx = min(max(bx + lx - 2, 0), W_IMG - 1);
        float v = x[gy * W_IMG + gx];
        simg[ly][lx] = fminf(fmaxf(floorf(v * 255.0f), 0.0f), 255.0f);
    }
    __syncthreads();

    // Magnitude over (TY+2) x (TX+2) region (output tile + 1-halo)
    for (int i = tid; i < (TY + 2) * (TX + 2); i += NT) {
        int ly = i / (TX + 2), lx = i % (TX + 2);
        int cy = ly + 1, cx = lx + 1;
        float gxv = (simg[cy - 1][cx + 1] + 2.0f * simg[cy][cx + 1] + simg[cy + 1][cx + 1])
                  - (simg[cy - 1][cx - 1] + 2.0f * simg[cy][cx - 1] + simg[cy + 1][cx - 1]);
        float gyv = (simg[cy + 1][cx - 1] + 2.0f * simg[cy + 1][cx] + simg[cy + 1][cx + 1])
                  - (simg[cy - 1][cx - 1] + 2.0f * simg[cy - 1][cx] + simg[cy - 1][cx + 1]);
        smag[ly][lx] = fabsf(gxv) + fabsf(gyv);
    }
    __syncthreads();

    // NMS for this thread's output pixel
    const int ox = bx + tx, oy = by + ty;
    const int cy = ty + 2, cx = tx + 2;  // center in simg coords
    float gxv = (simg[cy - 1][cx + 1] + 2.0f * simg[cy][cx + 1] + simg[cy + 1][cx + 1])
              - (simg[cy - 1][cx - 1] + 2.0f * simg[cy][cx - 1] + simg[cy + 1][cx - 1]);
    float gyv = (simg[cy + 1][cx - 1] + 2.0f * simg[cy + 1][cx] + simg[cy + 1][cx + 1])
              - (simg[cy - 1][cx - 1] + 2.0f * simg[cy - 1][cx] + simg[cy - 1][cx + 1]);
    float m = fabsf(gxv) + fabsf(gyv);

    const float T1 = 0.41421356237309503f;  // tan(22.5 deg)
    const float T2 = 2.41421356237309510f;  // tan(67.5 deg)
    float agx = fabsf(gxv), agy = fabsf(gyv);
    float n1, n2;
    if (agy < agx * T1) {                 // ~0 deg: compare L/R
        n1 = smag[ty + 1][tx + 2];
        n2 = smag[ty + 1][tx];
    } else if (agy > agx * T2) {          // ~90 deg: compare U/D
        n1 = smag[ty][tx + 1];
        n2 = smag[ty + 2][tx + 1];
    } else if (gxv * gyv > 0.0f) {        // ~45 deg
        n1 = smag[ty][tx + 2];
        n2 = smag[ty + 2][tx];
    } else {                              // ~135 deg
        n1 = smag[ty][tx];
        n2 = smag[ty + 2][tx + 2];
    }
    // (gx==gy==0 handled implicitly: m=0 > n2>=0 is false -> not kept)

    bool interior = (ox >= 1) && (ox < W_IMG - 1) && (oy >= 1) && (oy < H_IMG - 1);
    unsigned char st = 0;
    if (interior && (m >= n1) && (m > n2)) {
        if (m > 200.0f)      st = 3;  // strong
        else if (m > 100.0f) st = 1;  // weak
    }
    g_state[oy * W_IMG + ox] = st;
}

// ---------------------------------------------------------------------------
// K2: expand from every strong pixel (DFS through weak; spills to queue)
// ---------------------------------------------------------------------------
__global__ void k_seed() {
    unsigned i = blockIdx.x * blockDim.x + threadIdx.x;  // group of 4 pixels
    if (i >= NPIX / 4) return;
    uchar4 s = reinterpret_cast<const uchar4*>(g_state)[i];
    unsigned p0 = i * 4u;
    if (s.x == 3u) dfs_expand(p0);
    if (s.y == 3u) dfs_expand(p0 + 1u);
    if (s.z == 3u) dfs_expand(p0 + 2u);
    if (s.w == 3u) dfs_expand(p0 + 3u);
}

// ---------------------------------------------------------------------------
// K3: drain the overflow queue. Warp-batched claims; termination when
// processed == tail (reads ordered processed-then-tail; monotone counters
// make the equality a proof of quiescence). Warp-uniform control flow.
// ---------------------------------------------------------------------------
__global__ void k_bfs() {
    const unsigned FULL = 0xFFFFFFFFu;
    const int lane = threadIdx.x & 31;
    for (;;) {
        unsigned base = 0;
        if (lane == 0) base = atomicAdd(&g_head, 32u);
        base = __shfl_sync(FULL, base, 0);
        unsigned idx = base + (unsigned)lane;
        bool pending = true;
        for (;;) {
            unsigned t = *(volatile unsigned*)&g_tail;
            bool avail = pending && (idx < t);
            if (avail) {
                unsigned v;
                while ((v = *(volatile unsigned*)&g_queue[idx]) == 0u) __nanosleep(40);
                g_queue[idx] = 0u;  // restore zero for the next graph replay
                dfs_expand(v - 1u);
                pending = false;
            }
            unsigned cnt = __popc(__ballot_sync(FULL, avail));
            if (cnt) {
                __threadfence();
                if (lane == 0) atomicAdd(&g_processed, cnt);
            }
            if (!__any_sync(FULL, pending)) break;  // whole chunk done -> claim next

            // warp-uniform termination check (lane 0 reads, broadcast)
            unsigned p2 = 0, t2 = 0;
            if (lane == 0) {
                p2 = *(volatile unsigned*)&g_processed;
                __threadfence();
                t2 = *(volatile unsigned*)&g_tail;
            }
            p2 = __shfl_sync(FULL, p2, 0);
            t2 = __shfl_sync(FULL, t2, 0);
            if (p2 == t2) return;  // quiescent: no items left, none can appear
            __nanosleep(100);
        }
    }
}

// ---------------------------------------------------------------------------
// K4: write 3-channel float output (1.0 where state >= 2)
// ---------------------------------------------------------------------------
__global__ void k_write(float* __restrict__ out) {
    unsigned i = blockIdx.x * blockDim.x + threadIdx.x;
    if (i >= NPIX / 4) return;
    uchar4 s = reinterpret_cast<const uchar4*>(g_state)[i];
    float4 f;
    f.x = (s.x >= 2u) ? 1.0f : 0.0f;
    f.y = (s.y >= 2u) ? 1.0f : 0.0f;
    f.z = (s.z >= 2u) ? 1.0f : 0.0f;
    f.w = (s.w >= 2u) ? 1.0f : 0.0f;
    float4* o = reinterpret_cast<float4*>(out);
    o[i] = f;
    o[i + NPIX / 4] = f;
    o[i + 2 * (NPIX / 4)] = f;
}

// ---------------------------------------------------------------------------
extern "C" void kernel_launch(void* const* d_in, const int* in_sizes, int n_in,
                              void* d_out, int out_size) {
    const float* x = (const float*)d_in[0];
    float* out = (float*)d_out;

    k_reset<<<1, 1>>>();
    k_grad<<<dim3(W_IMG / TX, H_IMG / TY), dim3(TX, TY)>>>(x);
    k_seed<<<(NPIX / 4 + 255) / 256, 256>>>();
    k_bfs<<<64, 128>>>();
    k_write<<<(NPIX / 4 + 255) / 256, 256>>>(out);
}

// round 2
// speedup vs baseline: 1.1810x; 1.1810x over previous
#include <cuda_runtime.h>

#define W_IMG 2048
#define H_IMG 2048
#define NPIX (W_IMG * H_IMG)
#define WW 64                     // 32-bit words per image row
#define NWORDS (WW * H_IMG)       // 131072 words

// bitmasks: bit i of word (r*WW + c) = pixel (r, c*32 + i)
__device__ unsigned g_W[NWORDS];          // weak-or-strong candidate mask
__device__ unsigned g_E[NWORDS];          // edge mask (init = strong, grows)
__device__ unsigned g_dirty[NWORDS / 32]; // in-queue dedup bits (self-restoring)
#define QCAP (1u << 21)
__device__ unsigned g_queue[QCAP];        // zero at load; consumers re-zero slots
__device__ unsigned g_tail, g_head, g_processed;

// horizontal dilation of word m with left/right neighbor words l, r
__device__ __forceinline__ unsigned dilw(unsigned l, unsigned m, unsigned r) {
    return m | (m << 1) | (m >> 1) | (l >> 31) | (r << 31);
}

__device__ __forceinline__ void push_word(int r, int c) {
    if ((unsigned)r >= H_IMG || (unsigned)c >= WW) return;
    unsigned w = (unsigned)(r * WW + c);
    unsigned bit = 1u << (w & 31u);
    unsigned old = atomicOr(&g_dirty[w >> 5], bit);
    if (!(old & bit)) {
        unsigned pos = atomicAdd(&g_tail, 1u);
        ((volatile unsigned*)g_queue)[pos & (QCAP - 1u)] = w + 1u; // publish nonzero
    }
}

// ---------------------------------------------------------------------------
// K1: quantize + Sobel + L1 mag + NMS + double threshold -> W, E bitmasks
// ---------------------------------------------------------------------------
#define TX 32
#define TY 16

__global__ __launch_bounds__(TX* TY) void k_grad(const float* __restrict__ x) {
    __shared__ float simg[TY + 4][TX + 4];
    __shared__ float smag[TY + 2][TX + 2 + 1];

    const int tx = threadIdx.x, ty = threadIdx.y;
    const int bx = blockIdx.x * TX, by = blockIdx.y * TY;
    const int tid = ty * TX + tx;
    const int NT = TX * TY;

    if (blockIdx.x == 0 && blockIdx.y == 0 && tid == 0) {
        g_tail = 0u; g_head = 0u; g_processed = 0u;
    }

    for (int i = tid; i < (TY + 4) * (TX + 4); i += NT) {
        int ly = i / (TX + 4), lx = i % (TX + 4);
        int gy = min(max(by + ly - 2, 0), H_IMG - 1);
        int gx = min(max(bx + lx - 2, 0), W_IMG - 1);
        float v = x[gy * W_IMG + gx];
        simg[ly][lx] = fminf(fmaxf(floorf(v * 255.0f), 0.0f), 255.0f);
    }
    __syncthreads();

    for (int i = tid; i < (TY + 2) * (TX + 2); i += NT) {
        int ly = i / (TX + 2), lx = i % (TX + 2);
        int cy = ly + 1, cx = lx + 1;
        float gxv = (simg[cy - 1][cx + 1] + 2.0f * simg[cy][cx + 1] + simg[cy + 1][cx + 1])
                  - (simg[cy - 1][cx - 1] + 2.0f * simg[cy][cx - 1] + simg[cy + 1][cx - 1]);
        float gyv = (simg[cy + 1][cx - 1] + 2.0f * simg[cy + 1][cx] + simg[cy + 1][cx + 1])
                  - (simg[cy - 1][cx - 1] + 2.0f * simg[cy - 1][cx] + simg[cy - 1][cx + 1]);
        smag[ly][lx] = fabsf(gxv) + fabsf(gyv);
    }
    __syncthreads();

    const int ox = bx + tx, oy = by + ty;
    const int cy = ty + 2, cx = tx + 2;
    float gxv = (simg[cy - 1][cx + 1] + 2.0f * simg[cy][cx + 1] + simg[cy + 1][cx + 1])
              - (simg[cy - 1][cx - 1] + 2.0f * simg[cy][cx - 1] + simg[cy + 1][cx - 1]);
    float gyv = (simg[cy + 1][cx - 1] + 2.0f * simg[cy + 1][cx] + simg[cy + 1][cx + 1])
              - (simg[cy - 1][cx - 1] + 2.0f * simg[cy - 1][cx] + simg[cy - 1][cx + 1]);
    float m = fabsf(gxv) + fabsf(gyv);

    const float T1 = 0.41421356237309503f;  // tan(22.5)
    const float T2 = 2.41421356237309510f;  // tan(67.5)
    float agx = fabsf(gxv), agy = fabsf(gyv);
    float n1, n2;
    if (agy < agx * T1) {
        n1 = smag[ty + 1][tx + 2]; n2 = smag[ty + 1][tx];
    } else if (agy > agx * T2) {
        n1 = smag[ty][tx + 1];     n2 = smag[ty + 2][tx + 1];
    } else if (gxv * gyv > 0.0f) {
        n1 = smag[ty][tx + 2];     n2 = smag[ty + 2][tx];
    } else {
        n1 = smag[ty][tx];         n2 = smag[ty + 2][tx + 2];
    }

    bool interior = (ox >= 1) && (ox < W_IMG - 1) && (oy >= 1) && (oy < H_IMG - 1);
    bool keep = interior && (m >= n1) && (m > n2);
    bool strong = keep && (m > 200.0f);
    bool weak   = keep && (m > 100.0f);   // includes strong

    unsigned wb = __ballot_sync(0xFFFFFFFFu, weak);
    unsigned sb = __ballot_sync(0xFFFFFFFFu, strong);
    if (tx == 0) {
        int word = oy * WW + (ox >> 5);
        g_W[word] = wb;
        g_E[word] = sb;
    }
}

// ---------------------------------------------------------------------------
// K2: per-band bitboard hysteresis fixpoint in shared memory
// ---------------------------------------------------------------------------
#define BAND 16

__global__ __launch_bounds__(1024) void k_hyst() {
    __shared__ unsigned sE[BAND + 2][WW];
    __shared__ unsigned sW[BAND][WW];
    __shared__ int chg;

    const int tid = threadIdx.x;
    const int r0 = blockIdx.x * BAND;
    const int rr = tid >> 6, c = tid & 63;
    const int r = rr + 1;

    if (tid < WW) { sE[0][tid] = 0u; sE[BAND + 1][tid] = 0u; }
    sE[r][c] = g_E[(r0 + rr) * WW + c];
    sW[rr][c] = g_W[(r0 + rr) * WW + c];
    __syncthreads();

    const unsigned Wm = sW[rr][c];
    for (;;) {
        if (tid == 0) chg = 0;
        __syncthreads();
        unsigned cur = sE[r][c];
        unsigned ul = c ? sE[r - 1][c - 1] : 0u, um = sE[r - 1][c], ur = (c < 63) ? sE[r - 1][c + 1] : 0u;
        unsigned ml = c ? sE[r][c - 1] : 0u,                          mr = (c < 63) ? sE[r][c + 1] : 0u;
        unsigned dl = c ? sE[r + 1][c - 1] : 0u, dm = sE[r + 1][c], dr = (c < 63) ? sE[r + 1][c + 1] : 0u;
        unsigned d = dilw(ul, um, ur) | dilw(ml, cur, mr) | dilw(dl, dm, dr);
        unsigned nw = cur | (Wm & d);
        // in-word horizontal closure
        for (;;) {
            unsigned o = nw;
            nw |= Wm & ((nw << 1) | (nw >> 1));
            if (nw == o) break;
        }
        if (nw != cur) { sE[r][c] = nw; chg = 1; }
        __syncthreads();
        int done = (chg == 0);
        __syncthreads();
        if (done) break;
    }

    g_E[(r0 + rr) * WW + c] = sE[r][c];

    // cross-band seeds: conservative enqueue of adjacent-row words
    if (rr == 0 && r0 > 0) {
        unsigned act = dilw(c ? sE[1][c - 1] : 0u, sE[1][c], (c < 63) ? sE[1][c + 1] : 0u);
        if (act) push_word(r0 - 1, c);
    }
    if (rr == BAND - 1 && r0 + BAND < H_IMG) {
        unsigned act = dilw(c ? sE[BAND][c - 1] : 0u, sE[BAND][c], (c < 63) ? sE[BAND][c + 1] : 0u);
        if (act) push_word(r0 + BAND, c);
    }
}

// ---------------------------------------------------------------------------
// K3: drain — word-granularity propagation through the dedup'd queue
// ---------------------------------------------------------------------------
__device__ __forceinline__ unsigned ldE(int r, int c) {
    if ((unsigned)r >= H_IMG || (unsigned)c >= WW) return 0u;
    return *(volatile unsigned*)&g_E[r * WW + c];
}

__device__ void process_word(unsigned w) {
    int r = (int)(w >> 6), c = (int)(w & 63u);
    atomicAnd(&g_dirty[w >> 5], ~(1u << (w & 31u)));  // clear BEFORE reading state

    unsigned ul = ldE(r - 1, c - 1), um = ldE(r - 1, c), ur = ldE(r - 1, c + 1);
    unsigned ml = ldE(r, c - 1),     cur = ldE(r, c),    mr = ldE(r, c + 1);
    unsigned dl = ldE(r + 1, c - 1), dm = ldE(r + 1, c), dr = ldE(r + 1, c + 1);
    unsigned Wm = g_W[w];

    unsigned base = dilw(ul, um, ur) | dilw(ml, cur, mr) | dilw(dl, dm, dr);
    unsigned s = cur | (Wm & base);
    for (;;) {
        unsigned o = s;
        s |= Wm & ((s << 1) | (s >> 1));
        if (s == o) break;
    }
    unsigned delta = s & ~cur;
    if (delta) {
        unsigned prev = atomicOr(&g_E[w], delta);
        unsigned newly = delta & ~prev;
        if (newly) {
            __threadfence();
            push_word(r - 1, c);
            push_word(r + 1, c);
            if (newly & 1u) {
                push_word(r - 1, c - 1); push_word(r, c - 1); push_word(r + 1, c - 1);
            }
            if (newly & 0x80000000u) {
                push_word(r - 1, c + 1); push_word(r, c + 1); push_word(r + 1, c + 1);
            }
        }
    }
}

__global__ void k_drain() {
    const unsigned FULL = 0xFFFFFFFFu;
    const int lane = threadIdx.x & 31;
    for (;;) {
        unsigned base = 0;
        if (lane == 0) base = atomicAdd(&g_head, 32u);
        base = __shfl_sync(FULL, base, 0);
        unsigned idx = base + (unsigned)lane;
        bool pending = true;
        for (;;) {
            unsigned t = *(volatile unsigned*)&g_tail;
            bool avail = pending && (idx < t);
            if (avail) {
                unsigned slot = idx & (QCAP - 1u);
                unsigned v;
                while ((v = *(volatile unsigned*)&g_queue[slot]) == 0u) __nanosleep(40);
                g_queue[slot] = 0u;  // restore zero for next replay
                process_word(v - 1u);
                pending = false;
            }
            unsigned cnt = __popc(__ballot_sync(FULL, avail));
            if (cnt) {
                __threadfence();
                if (lane == 0) atomicAdd(&g_processed, cnt);
            }
            if (!__any_sync(FULL, pending)) break;

            unsigned p2 = 0, t2 = 0;
            if (lane == 0) {
                p2 = *(volatile unsigned*)&g_processed;
                __threadfence();
                t2 = *(volatile unsigned*)&g_tail;
            }
            p2 = __shfl_sync(FULL, p2, 0);
            t2 = __shfl_sync(FULL, t2, 0);
            if (p2 == t2) return;  // quiescent
            __nanosleep(100);
        }
    }
}

// ---------------------------------------------------------------------------
// K4: expand edge bitmask to 3 x H x W float output
// ---------------------------------------------------------------------------
__global__ void k_write(float* __restrict__ out) {
    unsigned i = blockIdx.x * blockDim.x + threadIdx.x;  // one float4 = 4 pixels
    if (i >= NPIX / 4) return;
    unsigned bits = (g_E[i >> 3] >> ((i & 7u) * 4u)) & 0xFu;
    float4 f;
    f.x = (bits & 1u) ? 1.0f : 0.0f;
    f.y = (bits & 2u) ? 1.0f : 0.0f;
    f.z = (bits & 4u) ? 1.0f : 0.0f;
    f.w = (bits & 8u) ? 1.0f : 0.0f;
    float4* o = reinterpret_cast<float4*>(out);
    o[i] = f;
    o[i + NPIX / 4] = f;
    o[i + 2 * (NPIX / 4)] = f;
}

// ---------------------------------------------------------------------------
extern "C" void kernel_launch(void* const* d_in, const int* in_sizes, int n_in,
                              void* d_out, int out_size) {
    const float* x = (const float*)d_in[0];
    float* out = (float*)d_out;

    k_grad<<<dim3(W_IMG / TX, H_IMG / TY), dim3(TX, TY)>>>(x);
    k_hyst<<<H_IMG / BAND, 1024>>>();
    k_drain<<<64, 128>>>();
    k_write<<<(NPIX / 4 + 255) / 256, 256>>>(out);
}

// round 3
// speedup vs baseline: 1.2522x; 1.0603x over previous
#include <cuda_runtime.h>

#define W_IMG 2048
#define H_IMG 2048
#define NPIX (W_IMG * H_IMG)
#define WW 64                     // 32-bit words per image row
#define NWORDS (WW * H_IMG)

// bitmasks: bit i of word (r*WW + c) = pixel (r, c*32 + i)
__device__ unsigned g_W[NWORDS];   // weak-or-strong candidate mask
__device__ unsigned g_E[NWORDS];   // edge mask (init = strong, grows)

// cooperative-kernel state (all self-restoring across graph replays)
__device__ unsigned g_bar_arrive;  // returns to 0 after every barrier
__device__ unsigned g_bar_gen;     // monotone generation counter (wrap-safe)
__device__ unsigned g_flag[2];     // per-round convergence flags (reset in-loop)

__device__ __forceinline__ unsigned dilw(unsigned l, unsigned m, unsigned r) {
    return m | (m << 1) | (m >> 1) | (l >> 31) | (r << 31);
}

// ---------------------------------------------------------------------------
// K1: quantize + Sobel + L1 mag + NMS + double threshold -> W, E bitmasks
// ---------------------------------------------------------------------------
#define TX 32
#define TY 16

__global__ __launch_bounds__(TX* TY) void k_grad(const float* __restrict__ x) {
    __shared__ float simg[TY + 4][TX + 4];
    __shared__ float smag[TY + 2][TX + 2 + 1];

    const int tx = threadIdx.x, ty = threadIdx.y;
    const int bx = blockIdx.x * TX, by = blockIdx.y * TY;
    const int tid = ty * TX + tx;
    const int NT = TX * TY;

    for (int i = tid; i < (TY + 4) * (TX + 4); i += NT) {
        int ly = i / (TX + 4), lx = i % (TX + 4);
        int gy = min(max(by + ly - 2, 0), H_IMG - 1);
        int gx = min(max(bx + lx - 2, 0), W_IMG - 1);
        float v = __ldg(&x[gy * W_IMG + gx]);
        simg[ly][lx] = fminf(fmaxf(floorf(v * 255.0f), 0.0f), 255.0f);
    }
    __syncthreads();

    for (int i = tid; i < (TY + 2) * (TX + 2); i += NT) {
        int ly = i / (TX + 2), lx = i % (TX + 2);
        int cy = ly + 1, cx = lx + 1;
        float gxv = (simg[cy - 1][cx + 1] + 2.0f * simg[cy][cx + 1] + simg[cy + 1][cx + 1])
                  - (simg[cy - 1][cx - 1] + 2.0f * simg[cy][cx - 1] + simg[cy + 1][cx - 1]);
        float gyv = (simg[cy + 1][cx - 1] + 2.0f * simg[cy + 1][cx] + simg[cy + 1][cx + 1])
                  - (simg[cy - 1][cx - 1] + 2.0f * simg[cy - 1][cx] + simg[cy - 1][cx + 1]);
        smag[ly][lx] = fabsf(gxv) + fabsf(gyv);
    }
    __syncthreads();

    const int ox = bx + tx, oy = by + ty;
    const int cy = ty + 2, cx = tx + 2;
    float gxv = (simg[cy - 1][cx + 1] + 2.0f * simg[cy][cx + 1] + simg[cy + 1][cx + 1])
              - (simg[cy - 1][cx - 1] + 2.0f * simg[cy][cx - 1] + simg[cy + 1][cx - 1]);
    float gyv = (simg[cy + 1][cx - 1] + 2.0f * simg[cy + 1][cx] + simg[cy + 1][cx + 1])
              - (simg[cy - 1][cx - 1] + 2.0f * simg[cy - 1][cx] + simg[cy - 1][cx + 1]);
    float m = fabsf(gxv) + fabsf(gyv);

    const float T1 = 0.41421356237309503f;  // tan(22.5)
    const float T2 = 2.41421356237309510f;  // tan(67.5)
    float agx = fabsf(gxv), agy = fabsf(gyv);
    float n1, n2;
    if (agy < agx * T1) {
        n1 = smag[ty + 1][tx + 2]; n2 = smag[ty + 1][tx];
    } else if (agy > agx * T2) {
        n1 = smag[ty][tx + 1];     n2 = smag[ty + 2][tx + 1];
    } else if (gxv * gyv > 0.0f) {
        n1 = smag[ty][tx + 2];     n2 = smag[ty + 2][tx];
    } else {
        n1 = smag[ty][tx];         n2 = smag[ty + 2][tx + 2];
    }

    bool interior = (ox >= 1) && (ox < W_IMG - 1) && (oy >= 1) && (oy < H_IMG - 1);
    bool keep = interior && (m >= n1) && (m > n2);
    bool strong = keep && (m > 200.0f);
    bool weak   = keep && (m > 100.0f);   // includes strong

    unsigned wb = __ballot_sync(0xFFFFFFFFu, weak);
    unsigned sb = __ballot_sync(0xFFFFFFFFu, strong);
    if (tx == 0) {
        int word = oy * WW + (ox >> 5);
        g_W[word] = wb;
        g_E[word] = sb;
    }
}

// ---------------------------------------------------------------------------
// K2: persistent cooperative hysteresis. 128 blocks (one wave), each owns a
// 16-row band; bitboard fixpoint in smem; cross-band exchange via boundary
// rows in g_E + custom grid barrier; global convergence via alternating flags.
// ---------------------------------------------------------------------------
#define BAND 16
#define NB (H_IMG / BAND)   // 128 blocks

__device__ __forceinline__ void grid_barrier() {
    __syncthreads();
    if (threadIdx.x == 0) {
        __threadfence();
        unsigned gen = *(volatile unsigned*)&g_bar_gen;
        unsigned a = atomicAdd(&g_bar_arrive, 1u);
        if (a == NB - 1) {
            g_bar_arrive = 0u;
            __threadfence();
            atomicAdd(&g_bar_gen, 1u);   // release next generation
        } else {
            while (*(volatile unsigned*)&g_bar_gen == gen) __nanosleep(20);
        }
        __threadfence();
    }
    __syncthreads();
}

__global__ __launch_bounds__(1024, 1) void k_hyst() {
    __shared__ unsigned sE[BAND + 2][WW];
    __shared__ unsigned sW[BAND][WW];

    const int tid = threadIdx.x;
    const int r0 = blockIdx.x * BAND;
    const int rr = tid >> 6, c = tid & 63;
    const int r = rr + 1;

    if (tid < WW) { sE[0][tid] = 0u; sE[BAND + 1][tid] = 0u; }
    sE[r][c] = g_E[(r0 + rr) * WW + c];
    sW[rr][c] = g_W[(r0 + rr) * WW + c];
    __syncthreads();

    const unsigned Wm = sW[rr][c];

    // one relaxation pass; returns block-wide "anything changed"
    auto pass = [&]() -> int {
        unsigned cur = sE[r][c];
        unsigned ul = c ? sE[r - 1][c - 1] : 0u, um = sE[r - 1][c], ur = (c < 63) ? sE[r - 1][c + 1] : 0u;
        unsigned ml = c ? sE[r][c - 1] : 0u,                          mr = (c < 63) ? sE[r][c + 1] : 0u;
        unsigned dl = c ? sE[r + 1][c - 1] : 0u, dm = sE[r + 1][c], dr = (c < 63) ? sE[r + 1][c + 1] : 0u;
        unsigned d = dilw(ul, um, ur) | dilw(ml, cur, mr) | dilw(dl, dm, dr);
        unsigned nw = cur | (Wm & d);
        for (;;) {  // in-word horizontal closure
            unsigned o = nw;
            nw |= Wm & ((nw << 1) | (nw >> 1));
            if (nw == o) break;
        }
        int ch = (nw != cur);
        if (ch) sE[r][c] = nw;
        return __syncthreads_or(ch);
    };

    while (pass()) {}  // initial local fixpoint

    for (int p = 0;; p ^= 1) {
        // publish boundary rows (device-scope visible; ordered by barrier fences)
        if (rr == 0)        *(volatile unsigned*)&g_E[r0 * WW + c] = sE[1][c];
        if (rr == BAND - 1) *(volatile unsigned*)&g_E[(r0 + BAND - 1) * WW + c] = sE[BAND][c];
        grid_barrier();
        // read fresh halos (L1-bypassing loads)
        if (tid < WW) {
            sE[0][tid] = (r0 > 0) ? *(volatile unsigned*)&g_E[(r0 - 1) * WW + tid] : 0u;
            sE[BAND + 1][tid] = (r0 + BAND < H_IMG)
                ? *(volatile unsigned*)&g_E[(r0 + BAND) * WW + tid] : 0u;
        }
        __syncthreads();

        int changed = pass();
        if (changed) {
            atomicOr(&g_flag[p], 1u);
            while (pass()) {}   // relax to local fixpoint again
        }
        grid_barrier();
        unsigned f = *(volatile unsigned*)&g_flag[p];
        if (blockIdx.x == 0 && tid == 0) g_flag[p ^ 1] = 0u;  // pre-reset for next round
        if (!f) break;   // uniform across all blocks -> all exit together
    }

    // final state out
    g_E[(r0 + rr) * WW + c] = sE[r][c];
}

// ---------------------------------------------------------------------------
// K3: expand edge bitmask to 3 x H x W float output via smem staging + TMA
// bulk stores (bypasses the L1 store-wavefront bottleneck).
// Block = 256 threads, handles 4 rows (8192 px = 32 KB per plane).
// ---------------------------------------------------------------------------
__global__ __launch_bounds__(256) void k_write(float* __restrict__ out) {
    __shared__ __align__(16) float sbuf[4 * W_IMG];   // 32 KB

    const unsigned FULL = 0xFFFFFFFFu;
    const int r0 = blockIdx.x * 4;
    const int warp = threadIdx.x >> 5, lane = threadIdx.x & 31;

    // warp w handles pixels [w*1024, (w+1)*1024) of the 8192-px tile
    unsigned wrd = g_E[r0 * WW + warp * 32 + lane];

#pragma unroll
    for (int j = 0; j < 8; j++) {
        // float4 index within warp chunk: j*32 + lane  -> pixels 4*(j*32+lane)
        unsigned srcw = __shfl_sync(FULL, wrd, j * 4 + (lane >> 3));
        unsigned bits = (srcw >> ((lane & 7u) * 4u)) & 0xFu;
        float4 f;
        f.x = (bits & 1u) ? 1.0f : 0.0f;
        f.y = (bits & 2u) ? 1.0f : 0.0f;
        f.z = (bits & 4u) ? 1.0f : 0.0f;
        f.w = (bits & 8u) ? 1.0f : 0.0f;
        reinterpret_cast<float4*>(sbuf)[warp * 256 + j * 32 + lane] = f;
    }
    __syncthreads();
    asm volatile("fence.proxy.async.shared::cta;" ::: "memory");

    if (threadIdx.x == 0) {
        unsigned saddr = (unsigned)__cvta_generic_to_shared(sbuf);
#pragma unroll
        for (int plane = 0; plane < 3; plane++) {
            float* dst = out + (size_t)plane * NPIX + (size_t)r0 * W_IMG;
            asm volatile(
                "cp.async.bulk.global.shared::cta.bulk_group [%0], [%1], %2;"
                :: "l"(dst), "r"(saddr), "n"(4 * W_IMG * 4) : "memory");
        }
        asm volatile("cp.async.bulk.commit_group;" ::: "memory");
        asm volatile("cp.async.bulk.wait_group 0;" ::: "memory");
    }
}

// ---------------------------------------------------------------------------
extern "C" void kernel_launch(void* const* d_in, const int* in_sizes, int n_in,
                              void* d_out, int out_size) {
    const float* x = (const float*)d_in[0];
    float* out = (float*)d_out;

    k_grad<<<dim3(W_IMG / TX, H_IMG / TY), dim3(TX, TY)>>>(x);
    k_hyst<<<NB, 1024>>>();
    k_write<<<H_IMG / 4, 256>>>(out);
}

// round 4
// speedup vs baseline: 1.4346x; 1.1456x over previous
#include <cuda_runtime.h>

#define W_IMG 2048
#define H_IMG 2048
#define NPIX (W_IMG * H_IMG)
#define WW 64                     // 32-bit words per image row
#define NWORDS (WW * H_IMG)

__device__ unsigned g_W[NWORDS];   // weak-or-strong candidate mask
__device__ unsigned g_E[NWORDS];   // edge mask (strong seeds; boundary exchange)

// cooperative-kernel state (self-restoring across graph replays)
__device__ unsigned g_bar_arrive;
__device__ unsigned g_bar_gen;
__device__ unsigned g_flag[2];

__device__ __forceinline__ unsigned dilw(unsigned l, unsigned m, unsigned r) {
    return m | (m << 1) | (m >> 1) | (l >> 31) | (r << 31);
}

// full in-word horizontal flood of seeds s through mask W (s subset of W)
__device__ __forceinline__ unsigned hclose(unsigned s, unsigned W) {
    unsigned up = W & ((W + s) ^ W);          // carry-ripple toward MSB
    unsigned rs = __brev(s), rW = __brev(W);
    unsigned dn = __brev(rW & ((rW + rs) ^ rW));
    return s | up | dn;
}

// ---------------------------------------------------------------------------
// K1: streaming separable Sobel + NMS + double threshold -> W/E bitmasks.
// Block: 256 threads = 256 columns; 32 output rows per block; 1 sync/row.
// ---------------------------------------------------------------------------
#define CB 256
#define RPB 32

__device__ __forceinline__ float quant(float v) {
    return fminf(fmaxf(floorf(v * 255.0f), 0.0f), 255.0f);
}

__global__ __launch_bounds__(256) void k_grad(const float* __restrict__ x) {
    __shared__ float2 st12[2][CB + 4];   // t1,t2 for cols c0-2 .. c0+CB+1
    __shared__ float  smag[4][CB + 2];   // mag ring, cols c0-1 .. c0+CB

    const int tid = threadIdx.x;
    const int c0 = blockIdx.x * CB;
    const int y0 = blockIdx.y * RPB;
    const int xm = c0 + tid;
    const int jt = tid + 2;              // t12 index of main column

    // extra t12 column duty (4 threads)
    bool he = false; int je = 0, xe = 0;
    if (tid == 0)        { he = true; je = 0;      xe = c0 - 2; }
    else if (tid == 1)   { he = true; je = 1;      xe = c0 - 1; }
    else if (tid == 254) { he = true; je = CB + 2; xe = c0 + CB; }
    else if (tid == 255) { he = true; je = CB + 3; xe = c0 + CB + 1; }
    xe = min(max(xe, 0), W_IMG - 1);
    const bool hm = (tid == 0) || (tid == 255);     // extra mag column duty
    const int jme = (tid == 0) ? 0 : CB + 1;

    const float T1 = 0.41421356237309503f;  // tan(22.5)
    const float T2 = 2.41421356237309510f;  // tan(67.5)

    // prologue: rows y0-2, y0-1, y0 (clamped)
    float a  = quant(x[min(max(y0 - 2, 0), H_IMG - 1) * W_IMG + xm]);
    float b  = quant(x[min(max(y0 - 1, 0), H_IMG - 1) * W_IMG + xm]);
    float cc = quant(x[min(y0, H_IMG - 1) * W_IMG + xm]);
    float ae = 0, be = 0, ce = 0;
    if (he) {
        ae = quant(x[min(max(y0 - 2, 0), H_IMG - 1) * W_IMG + xe]);
        be = quant(x[min(max(y0 - 1, 0), H_IMG - 1) * W_IMG + xe]);
        ce = quant(x[min(y0, H_IMG - 1) * W_IMG + xe]);
    }

    float gx1 = 0, gy1 = 0, mg1 = 0, gx2 = 0, gy2 = 0, mg2 = 0;

    for (int i = 0; i < RPB + 3; i++) {
        const int m = y0 - 1 + i;        // t12/mag row this iteration
        // prefetch next image row
        const int yn = min(max(m + 2, 0), H_IMG - 1);
        float cn = quant(__ldg(&x[yn * W_IMG + xm]));
        float cne = 0;
        if (he) cne = quant(__ldg(&x[yn * W_IMG + xe]));

        st12[i & 1][jt] = make_float2(a + 2.0f * b + cc, cc - a);
        if (he) st12[i & 1][je] = make_float2(ae + 2.0f * be + ce, ce - ae);
        __syncthreads();

        // mag row m (main column): mag idx j = tid+1 uses t12 idx j..j+2
        float2 lv = st12[i & 1][jt - 1];
        float2 mv = st12[i & 1][jt];
        float2 rv = st12[i & 1][jt + 1];
        float gx = rv.x - lv.x;
        float gy = lv.y + 2.0f * mv.y + rv.y;
        float mg = fabsf(gx) + fabsf(gy);
        smag[i & 3][tid + 1] = mg;
        if (hm) {
            float2 l2 = st12[i & 1][jme];
            float2 m2 = st12[i & 1][jme + 1];
            float2 r2 = st12[i & 1][jme + 2];
            smag[i & 3][jme] = fabsf(r2.x - l2.x) + fabsf(l2.y + 2.0f * m2.y + r2.y);
        }

        // NMS of row p = m-2 (uses regs from 2 iterations ago)
        if (i >= 3) {
            const int p = m - 2;
            float agx = fabsf(gx2), agy = fabsf(gy2);
            bool d0 = agy < agx * T1;
            bool d2 = agy > agx * T2;
            bool dg = (gx2 * gy2) > 0.0f;
            int dy1 = d0 ? 0 : -1;
            int dx1 = d0 ? 1 : (d2 ? 0 : (dg ? 1 : -1));
            float n1 = smag[(i - 2 + dy1) & 3][tid + 1 + dx1];
            float n2 = smag[(i - 2 - dy1) & 3][tid + 1 - dx1];
            bool interior = (p >= 1) && (p <= H_IMG - 2) && (xm >= 1) && (xm <= W_IMG - 2);
            bool keep = interior && (mg2 >= n1) && (mg2 > n2);
            bool strong = keep && (mg2 > 200.0f);
            bool weak   = keep && (mg2 > 100.0f);
            unsigned wb = __ballot_sync(0xFFFFFFFFu, weak);
            unsigned sb = __ballot_sync(0xFFFFFFFFu, strong);
            if ((tid & 31) == 0) {
                int wi = p * WW + (xm >> 5);
                g_W[wi] = wb;
                g_E[wi] = sb;
            }
        }

        gx2 = gx1; gy2 = gy1; mg2 = mg1;
        gx1 = gx;  gy1 = gy;  mg1 = mg;
        a = b; b = cc; cc = cn;
        if (he) { ae = be; be = ce; ce = cne; }
    }
}

// ---------------------------------------------------------------------------
// K2: persistent cooperative hysteresis + fused TMA writeout.
// 128 blocks (one wave); each owns a 16-row band in smem; O(1) in-word flood;
// cross-band exchange via boundary rows in g_E + custom grid barrier.
// ---------------------------------------------------------------------------
#define BAND 16
#define NB (H_IMG / BAND)

__device__ __forceinline__ void grid_barrier() {
    __syncthreads();
    if (threadIdx.x == 0) {
        __threadfence();
        unsigned gen = *(volatile unsigned*)&g_bar_gen;
        unsigned a = atomicAdd(&g_bar_arrive, 1u);
        if (a == NB - 1) {
            g_bar_arrive = 0u;
            __threadfence();
            atomicAdd(&g_bar_gen, 1u);
        } else {
            while (*(volatile unsigned*)&g_bar_gen == gen) __nanosleep(20);
        }
        __threadfence();
    }
    __syncthreads();
}

__global__ __launch_bounds__(1024, 1) void k_hyst(float* __restrict__ out) {
    __shared__ unsigned sE[BAND + 2][WW + 2];          // col 0 / WW+1 are zero halos
    __shared__ __align__(16) float4 sbuf[4 * W_IMG / 4];  // 32 KB staging (4 rows)

    const int tid = threadIdx.x;
    const int r0 = blockIdx.x * BAND;
    const int rr = tid >> 6, c = tid & 63;
    const int r = rr + 1, cc = c + 1;

    if (tid < BAND + 2) { sE[tid][0] = 0u; sE[tid][WW + 1] = 0u; }
    if (tid < WW) { sE[0][tid + 1] = 0u; sE[BAND + 1][tid + 1] = 0u; }
    sE[r][cc] = g_E[(r0 + rr) * WW + c];
    const unsigned Wm = g_W[(r0 + rr) * WW + c];
    __syncthreads();

    auto pass = [&]() -> int {
        unsigned cur = sE[r][cc];
        unsigned d = dilw(sE[r - 1][cc - 1], sE[r - 1][cc], sE[r - 1][cc + 1])
                   | dilw(sE[r][cc - 1],     cur,           sE[r][cc + 1])
                   | dilw(sE[r + 1][cc - 1], sE[r + 1][cc], sE[r + 1][cc + 1]);
        unsigned nw = hclose(cur | (Wm & d), Wm);
        int ch = (nw != cur);
        if (ch) sE[r][cc] = nw;
        return __syncthreads_or(ch);
    };

    while (pass()) {}

    for (int p = 0;; p ^= 1) {
        if (rr == 0)        *(volatile unsigned*)&g_E[r0 * WW + c] = sE[1][cc];
        if (rr == BAND - 1) *(volatile unsigned*)&g_E[(r0 + BAND - 1) * WW + c] = sE[BAND][cc];
        grid_barrier();
        if (tid < WW) {
            sE[0][tid + 1] = (r0 > 0) ? *(volatile unsigned*)&g_E[(r0 - 1) * WW + tid] : 0u;
            sE[BAND + 1][tid + 1] = (r0 + BAND < H_IMG)
                ? *(volatile unsigned*)&g_E[(r0 + BAND) * WW + tid] : 0u;
        }
        __syncthreads();

        int changed = pass();
        if (changed) {
            atomicOr(&g_flag[p], 1u);
            while (pass()) {}
        }
        grid_barrier();
        unsigned f = *(volatile unsigned*)&g_flag[p];
        if (blockIdx.x == 0 && tid == 0) g_flag[p ^ 1] = 0u;
        if (!f) break;
    }

    // ---- fused writeout: expand sE band -> 3 planes via TMA bulk stores ----
    for (int k = 0; k < 4; k++) {               // 4 chunks of 4 rows
        const int rb = k * 4;
#pragma unroll
        for (int t = 0; t < 2; t++) {
            int f = tid + t * 1024;             // float4 index in chunk (0..2047)
            int row = f >> 9;                   // 0..3
            int x4 = f & 511;
            unsigned bits = (sE[rb + row + 1][1 + (x4 >> 3)] >> ((x4 & 7u) * 4u)) & 0xFu;
            float4 v;
            v.x = (bits & 1u) ? 1.0f : 0.0f;
            v.y = (bits & 2u) ? 1.0f : 0.0f;
            v.z = (bits & 4u) ? 1.0f : 0.0f;
            v.w = (bits & 8u) ? 1.0f : 0.0f;
            sbuf[f] = v;
        }
        __syncthreads();
        if (tid == 0) {
            asm volatile("fence.proxy.async.shared::cta;" ::: "memory");
            unsigned saddr = (unsigned)__cvta_generic_to_shared(sbuf);
#pragma unroll
            for (int plane = 0; plane < 3; plane++) {
                float* dst = out + (size_t)plane * NPIX + (size_t)(r0 + rb) * W_IMG;
                asm volatile(
                    "cp.async.bulk.global.shared::cta.bulk_group [%0], [%1], %2;"
                    :: "l"(dst), "r"(saddr), "n"(4 * W_IMG * 4) : "memory");
            }
            asm volatile("cp.async.bulk.commit_group;" ::: "memory");
            asm volatile("cp.async.bulk.wait_group 0;" ::: "memory");
        }
        __syncthreads();
    }
}

// ---------------------------------------------------------------------------
extern "C" void kernel_launch(void* const* d_in, const int* in_sizes, int n_in,
                              void* d_out, int out_size) {
    const float* x = (const float*)d_in[0];
    float* out = (float*)d_out;

    k_grad<<<dim3(W_IMG / CB, H_IMG / RPB), 256>>>(x);
    k_hyst<<<NB, 1024>>>(out);
}

// round 5
// speedup vs baseline: 1.5809x; 1.1020x over previous
#include <cuda_runtime.h>

#define W_IMG 2048
#define H_IMG 2048
#define NPIX (W_IMG * H_IMG)
#define WW 64                     // 32-bit words per image row
#define NWORDS (WW * H_IMG)

__device__ unsigned g_W[NWORDS];   // weak-or-strong candidate mask
__device__ unsigned g_E[NWORDS];   // edge mask (strong seeds -> final edges)

// cooperative-kernel state (self-restoring across graph replays)
__device__ unsigned g_bar_arrive;
__device__ unsigned g_bar_gen;
__device__ unsigned g_flag[2];

__device__ __forceinline__ unsigned dilw(unsigned l, unsigned m, unsigned r) {
    return m | (m << 1) | (m >> 1) | (l >> 31) | (r << 31);
}

// full in-word horizontal flood of seeds s (subset of W) through mask W
__device__ __forceinline__ unsigned hclose(unsigned s, unsigned W) {
    unsigned up = W & ((W + s) ^ W);
    unsigned rs = __brev(s), rW = __brev(W);
    unsigned dn = __brev(rW & ((rW + rs) ^ rW));
    return s | up | dn;
}

// ---------------------------------------------------------------------------
// K1: streaming separable Sobel + NMS + double threshold -> W/E bitmasks.
// ---------------------------------------------------------------------------
#define CB 256
#define RPB 32

__device__ __forceinline__ float quant(float v) {
    return fminf(fmaxf(floorf(v * 255.0f), 0.0f), 255.0f);
}

__global__ __launch_bounds__(256) void k_grad(const float* __restrict__ x) {
    __shared__ float2 st12[2][CB + 4];
    __shared__ float  smag[4][CB + 2];

    const int tid = threadIdx.x;
    const int c0 = blockIdx.x * CB;
    const int y0 = blockIdx.y * RPB;
    const int xm = c0 + tid;
    const int jt = tid + 2;

    bool he = false; int je = 0, xe = 0;
    if (tid == 0)        { he = true; je = 0;      xe = c0 - 2; }
    else if (tid == 1)   { he = true; je = 1;      xe = c0 - 1; }
    else if (tid == 254) { he = true; je = CB + 2; xe = c0 + CB; }
    else if (tid == 255) { he = true; je = CB + 3; xe = c0 + CB + 1; }
    xe = min(max(xe, 0), W_IMG - 1);
    const bool hm = (tid == 0) || (tid == 255);
    const int jme = (tid == 0) ? 0 : CB + 1;

    const float T1 = 0.41421356237309503f;
    const float T2 = 2.41421356237309510f;

    float a  = quant(x[min(max(y0 - 2, 0), H_IMG - 1) * W_IMG + xm]);
    float b  = quant(x[min(max(y0 - 1, 0), H_IMG - 1) * W_IMG + xm]);
    float cc = quant(x[min(y0, H_IMG - 1) * W_IMG + xm]);
    float ae = 0, be = 0, ce = 0;
    if (he) {
        ae = quant(x[min(max(y0 - 2, 0), H_IMG - 1) * W_IMG + xe]);
        be = quant(x[min(max(y0 - 1, 0), H_IMG - 1) * W_IMG + xe]);
        ce = quant(x[min(y0, H_IMG - 1) * W_IMG + xe]);
    }

    float gx1 = 0, gy1 = 0, mg1 = 0, gx2 = 0, gy2 = 0, mg2 = 0;

    for (int i = 0; i < RPB + 3; i++) {
        const int m = y0 - 1 + i;
        const int yn = min(max(m + 2, 0), H_IMG - 1);
        float cn = quant(__ldg(&x[yn * W_IMG + xm]));
        float cne = 0;
        if (he) cne = quant(__ldg(&x[yn * W_IMG + xe]));

        st12[i & 1][jt] = make_float2(a + 2.0f * b + cc, cc - a);
        if (he) st12[i & 1][je] = make_float2(ae + 2.0f * be + ce, ce - ae);
        __syncthreads();

        float2 lv = st12[i & 1][jt - 1];
        float2 mv = st12[i & 1][jt];
        float2 rv = st12[i & 1][jt + 1];
        float gx = rv.x - lv.x;
        float gy = lv.y + 2.0f * mv.y + rv.y;
        float mg = fabsf(gx) + fabsf(gy);
        smag[i & 3][tid + 1] = mg;
        if (hm) {
            float2 l2 = st12[i & 1][jme];
            float2 m2 = st12[i & 1][jme + 1];
            float2 r2 = st12[i & 1][jme + 2];
            smag[i & 3][jme] = fabsf(r2.x - l2.x) + fabsf(l2.y + 2.0f * m2.y + r2.y);
        }

        if (i >= 3) {
            const int p = m - 2;
            float agx = fabsf(gx2), agy = fabsf(gy2);
            bool d0 = agy < agx * T1;
            bool d2 = agy > agx * T2;
            bool dg = (gx2 * gy2) > 0.0f;
            int dy1 = d0 ? 0 : -1;
            int dx1 = d0 ? 1 : (d2 ? 0 : (dg ? 1 : -1));
            float n1 = smag[(i - 2 + dy1) & 3][tid + 1 + dx1];
            float n2 = smag[(i - 2 - dy1) & 3][tid + 1 - dx1];
            bool interior = (p >= 1) && (p <= H_IMG - 2) && (xm >= 1) && (xm <= W_IMG - 2);
            bool keep = interior && (mg2 >= n1) && (mg2 > n2);
            bool strong = keep && (mg2 > 200.0f);
            bool weak   = keep && (mg2 > 100.0f);
            unsigned wb = __ballot_sync(0xFFFFFFFFu, weak);
            unsigned sb = __ballot_sync(0xFFFFFFFFu, strong);
            if ((tid & 31) == 0) {
                int wi = p * WW + (xm >> 5);
                g_W[wi] = wb;
                g_E[wi] = sb;
            }
        }

        gx2 = gx1; gy2 = gy1; mg2 = mg1;
        gx1 = gx;  gy1 = gy;  mg1 = mg;
        a = b; b = cc; cc = cn;
        if (he) { ae = be; be = ce; ce = cne; }
    }
}

// ---------------------------------------------------------------------------
// K2: persistent cooperative hysteresis. 64 blocks, 32-row bands,
// 2 rows/thread with intra-thread Gauss-Seidel; monotone benign races.
// ---------------------------------------------------------------------------
#define BAND 32
#define NB (H_IMG / BAND)   // 64

__device__ __forceinline__ void grid_barrier() {
    __syncthreads();
    if (threadIdx.x == 0) {
        __threadfence();
        unsigned gen = *(volatile unsigned*)&g_bar_gen;
        unsigned a = atomicAdd(&g_bar_arrive, 1u);
        if (a == NB - 1) {
            g_bar_arrive = 0u;
            __threadfence();
            atomicAdd(&g_bar_gen, 1u);
        } else {
            while (*(volatile unsigned*)&g_bar_gen == gen) __nanosleep(20);
        }
        __threadfence();
    }
    __syncthreads();
}

__global__ __launch_bounds__(1024, 1) void k_hyst() {
    __shared__ unsigned sE[BAND + 2][WW + 2];

    const int tid = threadIdx.x;
    const int q = tid >> 6, c = tid & 63;
    const int cc = c + 1;
    const int R = q * 2 + 1;                 // smem row of first owned row
    const int r0 = blockIdx.x * BAND;
    const int gw = (r0 + q * 2) * WW + c;    // global word idx of first owned row

    if (tid < BAND + 2) { sE[tid][0] = 0u; sE[tid][WW + 1] = 0u; }
    if (tid < WW) { sE[0][tid + 1] = 0u; sE[BAND + 1][tid + 1] = 0u; }

    unsigned a = g_E[gw];
    unsigned b = g_E[gw + WW];
    const unsigned W0 = g_W[gw];
    const unsigned W1 = g_W[gw + WW];
    sE[R][cc] = a; sE[R + 1][cc] = b;
    __syncthreads();

    auto pass = [&]() -> int {
        unsigned dU = dilw(sE[R - 1][cc - 1], sE[R - 1][cc], sE[R - 1][cc + 1]);
        unsigned dD = dilw(sE[R + 2][cc - 1], sE[R + 2][cc], sE[R + 2][cc + 1]);
        unsigned hA = dilw(sE[R][cc - 1],     a,             sE[R][cc + 1]);
        unsigned hB = dilw(sE[R + 1][cc - 1], b,             sE[R + 1][cc + 1]);
        // down sweep (Gauss-Seidel within the 2 owned rows)
        unsigned na = hclose(a | (W0 & (dU | hA | hB)), W0);
        unsigned hA2 = dilw(sE[R][cc - 1], na, sE[R][cc + 1]);
        unsigned nb = hclose(b | (W1 & (hA2 | hB | dD)), W1);
        // up sweep
        unsigned hB2 = dilw(sE[R + 1][cc - 1], nb, sE[R + 1][cc + 1]);
        unsigned na2 = hclose(na | (W0 & (dU | hA2 | hB2)), W0);
        int ch = (na2 != a) | (nb != b);
        if (na2 != a) { a = na2; sE[R][cc] = a; }
        if (nb != b)  { b = nb;  sE[R + 1][cc] = b; }
        return __syncthreads_or(ch);
    };

    while (pass()) {}   // local fixpoint

    for (int p = 0;; p ^= 1) {
        // publish band boundary rows
        if (q == 0)      *(volatile unsigned*)&g_E[r0 * WW + c] = a;
        if (q == 15)     *(volatile unsigned*)&g_E[(r0 + BAND - 1) * WW + c] = b;
        grid_barrier();
        // read fresh halos
        if (tid < WW) {
            sE[0][tid + 1] = (r0 > 0) ? *(volatile unsigned*)&g_E[(r0 - 1) * WW + tid] : 0u;
            sE[BAND + 1][tid + 1] = (r0 + BAND < H_IMG)
                ? *(volatile unsigned*)&g_E[(r0 + BAND) * WW + tid] : 0u;
        }
        __syncthreads();

        int changed = pass();
        if (changed) {
            atomicOr(&g_flag[p], 1u);
            while (pass()) {}
        }
        grid_barrier();
        unsigned f = *(volatile unsigned*)&g_flag[p];
        if (blockIdx.x == 0 && tid == 0) g_flag[p ^ 1] = 0u;
        if (!f) break;
    }

    // final masks out (coalesced)
    g_E[gw] = a;
    g_E[gw + WW] = b;
}

// ---------------------------------------------------------------------------
// K3: expand edge bitmask -> 3 x H x W float via smem staging + TMA bulk
// stores. 1024 blocks x 2 rows each: wide enough to hit the LTS/TMA cap.
// ---------------------------------------------------------------------------
#define WRB 2

__global__ __launch_bounds__(256) void k_write(float* __restrict__ out) {
    __shared__ __align__(16) float4 sbuf[WRB * 512];   // 16 KB

    const int r0 = blockIdx.x * WRB;
    const int t = threadIdx.x;

#pragma unroll
    for (int k = 0; k < WRB * 2; k++) {
        int f = t + k * 256;               // float4 index (0..1023)
        int row = f >> 9;
        int x4 = f & 511;
        unsigned w = g_E[(r0 + row) * WW + (x4 >> 3)];
        unsigned bits = (w >> ((x4 & 7u) * 4u)) & 0xFu;
        float4 v;
        v.x = (bits & 1u) ? 1.0f : 0.0f;
        v.y = (bits & 2u) ? 1.0f : 0.0f;
        v.z = (bits & 4u) ? 1.0f : 0.0f;
        v.w = (bits & 8u) ? 1.0f : 0.0f;
        sbuf[f] = v;
    }
    __syncthreads();

    if (t == 0) {
        asm volatile("fence.proxy.async.shared::cta;" ::: "memory");
        unsigned saddr = (unsigned)__cvta_generic_to_shared(sbuf);
#pragma unroll
        for (int plane = 0; plane < 3; plane++) {
            float* dst = out + (size_t)plane * NPIX + (size_t)r0 * W_IMG;
            asm volatile(
                "cp.async.bulk.global.shared::cta.bulk_group [%0], [%1], %2;"
                :: "l"(dst), "r"(saddr), "n"(WRB * W_IMG * 4) : "memory");
        }
        asm volatile("cp.async.bulk.commit_group;" ::: "memory");
        asm volatile("cp.async.bulk.wait_group 0;" ::: "memory");
    }
}

// ---------------------------------------------------------------------------
extern "C" void kernel_launch(void* const* d_in, const int* in_sizes, int n_in,
                              void* d_out, int out_size) {
    const float* x = (const float*)d_in[0];
    float* out = (float*)d_out;

    k_grad<<<dim3(W_IMG / CB, H_IMG / RPB), 256>>>(x);
    k_hyst<<<NB, 1024>>>();
    k_write<<<H_IMG / WRB, 256>>>(out);
}